// round 4
// baseline (speedup 1.0000x reference)
#include <cuda_runtime.h>
#include <cuda_fp16.h>
#include <cstdint>

// ============================================================================
// GhostLinear: out[M,N] = X[M,K] @ W^T,  W[N,K] = lut[indices]*scale
// M=16384, N=4096, K=4096
// Toolchain: PTX target sm_103 (no 'a') -> no tcgen05.ld -> legacy mma.sync.
// R3 evidence: HMMA rt ~8cyc/SMSP (1024 MAC/cyc/SM, floor 0.96ms); kernel was
// issue/convoy-bound at tensor=49.5% with 1 CTA/SM. R4: 2 CTAs/SM to overlap
// barrier+LDSM phases of one CTA with MMA of the other.
// ============================================================================

#define M_TOTAL 16384
#define N_TOTAL 4096
#define K_TOTAL 4096
#define CODES   256

#define BM 128
#define BN 128
#define BK 64
#define STAGES 3
#define NITER (K_TOTAL / BK)             // 64

#define BKP 72                            // padded halves per smem row (144 B)
#define A_STAGE_HALFS (BM * BKP)          // 9216
#define B_STAGE_HALFS (BN * BKP)          // 9216
#define STAGE_HALFS (A_STAGE_HALFS + B_STAGE_HALFS)      // 18432
#define SMEM_BYTES (STAGES * STAGE_HALFS * 2)            // 110592 -> 2 CTAs/SM

__device__ __align__(1024) __half g_X[(size_t)M_TOTAL * K_TOTAL];  // 128 MB
__device__ __align__(1024) __half g_W[(size_t)N_TOTAL * K_TOTAL];  //  32 MB

__device__ __forceinline__ uint32_t smem_u32(const void* p) {
    uint32_t a;
    asm("{ .reg .u64 t; cvta.to.shared.u64 t, %1; cvt.u32.u64 %0, t; }"
        : "=r"(a) : "l"(p));
    return a;
}

#define CP_ASYNC16(dst32, src) \
    asm volatile("cp.async.cg.shared.global [%0], [%1], 16;" \
                 :: "r"(dst32), "l"(src) : "memory")
#define CP_COMMIT() asm volatile("cp.async.commit_group;" ::: "memory")
#define CP_WAIT(n)  asm volatile("cp.async.wait_group %0;" :: "n"(n) : "memory")

#define LDSM4(r0, r1, r2, r3, addr) \
    asm volatile("ldmatrix.sync.aligned.m8n8.x4.shared.b16 {%0,%1,%2,%3}, [%4];" \
                 : "=r"(r0), "=r"(r1), "=r"(r2), "=r"(r3) : "r"(addr))

__device__ __forceinline__ void mma16816(float* c, const uint32_t* a, const uint32_t* b) {
    asm volatile(
        "mma.sync.aligned.m16n8k16.row.col.f32.f16.f16.f32 "
        "{%0,%1,%2,%3}, {%4,%5,%6,%7}, {%8,%9}, {%0,%1,%2,%3};"
        : "+f"(c[0]), "+f"(c[1]), "+f"(c[2]), "+f"(c[3])
        : "r"(a[0]), "r"(a[1]), "r"(a[2]), "r"(a[3]), "r"(b[0]), "r"(b[1]));
}

// ---------------------------------------------------------------------------
// Fused converter: blocks [0, XB) convert X fp32->fp16 (8/thread),
// blocks [XB, XB+WB) dequant W via codebook (4/thread).
// ---------------------------------------------------------------------------
#define XBLOCKS 32768
#define WBLOCKS 16384

__device__ __forceinline__ uint32_t h2u(__half2 h) {
    return *reinterpret_cast<uint32_t*>(&h);
}

__global__ void __launch_bounds__(256) convert_kernel(const float* __restrict__ x,
                                                      const int* __restrict__ idx,
                                                      const float* __restrict__ scale,
                                                      const float* __restrict__ lut) {
    if (blockIdx.x < XBLOCKS) {
        size_t i = ((size_t)blockIdx.x * 256 + threadIdx.x) * 8;
        float4 a = *reinterpret_cast<const float4*>(x + i);
        float4 b = *reinterpret_cast<const float4*>(x + i + 4);
        uint4 o;
        o.x = h2u(__floats2half2_rn(a.x, a.y));
        o.y = h2u(__floats2half2_rn(a.z, a.w));
        o.z = h2u(__floats2half2_rn(b.x, b.y));
        o.w = h2u(__floats2half2_rn(b.z, b.w));
        *reinterpret_cast<uint4*>(g_X + i) = o;
    } else {
        __shared__ float slut[CODES];
        if (threadIdx.x < CODES) slut[threadIdx.x] = lut[threadIdx.x];
        __syncthreads();
        size_t i = ((size_t)(blockIdx.x - XBLOCKS) * 256 + threadIdx.x) * 4;
        int4 v = *reinterpret_cast<const int4*>(idx + i);
        float s = scale[i >> 12];   // K_TOTAL elements per output row
        uint2 o;
        o.x = h2u(__floats2half2_rn(slut[v.x] * s, slut[v.y] * s));
        o.y = h2u(__floats2half2_rn(slut[v.z] * s, slut[v.w] * s));
        *reinterpret_cast<uint2*>(g_W + i) = o;
    }
}

// ---------------------------------------------------------------------------
// GEMM: CTA = 128(M) x 128(N), BK=64, 3-stage cp.async pipeline, 2 CTAs/SM.
// 256 threads = 8 warps in 4(M) x 2(N); warp tile 32 x 64.
// Fragments via ldmatrix.x4 (conflict-free: row stride 144B).
// ---------------------------------------------------------------------------
__global__ void __launch_bounds__(256, 2) gemm_kernel(const __half* __restrict__ X,
                                                      const __half* __restrict__ W,
                                                      float* __restrict__ out) {
    extern __shared__ __half sm[];
    const uint32_t smem_base = smem_u32(sm);
    const int tid  = threadIdx.x;
    const int lane = tid & 31;
    const int wid  = tid >> 5;
    const int warp_m = wid & 3;    // 32-row band
    const int warp_n = wid >> 2;   // 64-col band (0..1)
    const int m_base = blockIdx.y * BM;
    const int n_base = blockIdx.x * BN;

    // --- cp.async mapping: per thread 4 A chunks + 4 B chunks of 16B ---
    // A: 128 rows x 8 chunks = 1024; B: 128 rows x 8 chunks = 1024.
    const __half* gA[4]; uint32_t dA[4];
    const __half* gB[4]; uint32_t dB[4];
    #pragma unroll
    for (int q = 0; q < 4; q++) {
        int ai = tid * 4 + q;
        int ar = ai >> 3, ac = ai & 7;
        gA[q] = X + (size_t)(m_base + ar) * K_TOTAL + ac * 8;
        dA[q] = (uint32_t)(ar * BKP + ac * 8) * 2;
        gB[q] = W + (size_t)(n_base + ar) * K_TOTAL + ac * 8;
        dB[q] = (uint32_t)(A_STAGE_HALFS + ar * BKP + ac * 8) * 2;
    }

    // --- ldmatrix per-thread address components ---
    const int a_row_in  = warp_m * 32 + (lane & 15);
    const int a_koff_in = (lane >> 4) * 8;
    const int b_n_in    = warp_n * 64 + (lane & 7) + ((lane >> 4) & 1) * 8;
    const int b_koff_in = ((lane >> 3) & 1) * 8;

    float acc[2][8][4];
    #pragma unroll
    for (int t = 0; t < 2; t++)
        #pragma unroll
        for (int j = 0; j < 8; j++)
            #pragma unroll
            for (int e = 0; e < 4; e++) acc[t][j][e] = 0.f;

    // --- prologue: fill STAGES-1 stages ---
    #pragma unroll
    for (int s = 0; s < STAGES - 1; s++) {
        uint32_t sb = smem_base + (uint32_t)(s * STAGE_HALFS) * 2;
        int koff = s * BK;
        #pragma unroll
        for (int q = 0; q < 4; q++) CP_ASYNC16(sb + dA[q], gA[q] + koff);
        #pragma unroll
        for (int q = 0; q < 4; q++) CP_ASYNC16(sb + dB[q], gB[q] + koff);
        CP_COMMIT();
    }

    // --- main loop ---
    for (int kit = 0; kit < NITER; kit++) {
        CP_WAIT(STAGES - 2);
        __syncthreads();

        {   // prefetch stage kit + STAGES-1
            int pf = kit + STAGES - 1;
            if (pf < NITER) {
                uint32_t sb = smem_base + (uint32_t)((pf % STAGES) * STAGE_HALFS) * 2;
                int koff = pf * BK;
                #pragma unroll
                for (int q = 0; q < 4; q++) CP_ASYNC16(sb + dA[q], gA[q] + koff);
                #pragma unroll
                for (int q = 0; q < 4; q++) CP_ASYNC16(sb + dB[q], gB[q] + koff);
            }
            CP_COMMIT();
        }

        const uint32_t sb = smem_base + (uint32_t)((kit % STAGES) * STAGE_HALFS) * 2;
        const uint32_t sA = sb;
        const uint32_t sB = sb + A_STAGE_HALFS * 2;

        #pragma unroll
        for (int ks = 0; ks < 4; ks++) {        // four k16 steps in BK=64
            const int colk = ks * 16;
            uint32_t a[2][4], b[8][2];
            #pragma unroll
            for (int t = 0; t < 2; t++) {
                uint32_t addr = sA + (uint32_t)((a_row_in + t * 16) * BKP
                                              + colk + a_koff_in) * 2;
                LDSM4(a[t][0], a[t][1], a[t][2], a[t][3], addr);
            }
            #pragma unroll
            for (int jj = 0; jj < 4; jj++) {    // each x4 covers 2 n-tiles
                uint32_t addr = sB + (uint32_t)((b_n_in + jj * 16) * BKP
                                              + colk + b_koff_in) * 2;
                LDSM4(b[jj * 2][0], b[jj * 2][1], b[jj * 2 + 1][0], b[jj * 2 + 1][1], addr);
            }
            #pragma unroll
            for (int t = 0; t < 2; t++)
                #pragma unroll
                for (int j = 0; j < 8; j++)
                    mma16816(acc[t][j], a[t], b[j]);
        }
    }

    // --- epilogue ---
    #pragma unroll
    for (int t = 0; t < 2; t++) {
        int row = m_base + warp_m * 32 + t * 16 + (lane >> 2);
        #pragma unroll
        for (int j = 0; j < 8; j++) {
            int col = n_base + warp_n * 64 + j * 8 + (lane & 3) * 2;
            *reinterpret_cast<float2*>(out + (size_t)row * N_TOTAL + col) =
                make_float2(acc[t][j][0], acc[t][j][1]);
            *reinterpret_cast<float2*>(out + (size_t)(row + 8) * N_TOTAL + col) =
                make_float2(acc[t][j][2], acc[t][j][3]);
        }
    }
}

// ---------------------------------------------------------------------------
// Host launcher
// ---------------------------------------------------------------------------
extern "C" void kernel_launch(void* const* d_in, const int* in_sizes, int n_in,
                              void* d_out, int out_size) {
    (void)in_sizes; (void)n_in; (void)out_size;
    const float* x     = (const float*)d_in[0];
    const float* scale = (const float*)d_in[1];
    const float* lut   = (const float*)d_in[2];
    const int*   idx   = (const int*)d_in[3];
    float* out = (float*)d_out;

    void *pX = nullptr, *pW = nullptr;
    cudaGetSymbolAddress(&pX, g_X);
    cudaGetSymbolAddress(&pW, g_W);

    cudaFuncSetAttribute(gemm_kernel, cudaFuncAttributeMaxDynamicSharedMemorySize,
                         SMEM_BYTES);

    convert_kernel<<<XBLOCKS + WBLOCKS, 256>>>(x, idx, scale, lut);

    dim3 grid(N_TOTAL / BN, M_TOTAL / BM);   // (32, 128): x fastest -> A-band L2 reuse
    gemm_kernel<<<grid, 256, SMEM_BYTES>>>((const __half*)pX, (const __half*)pW, out);
}

// round 5
// speedup vs baseline: 1.0506x; 1.0506x over previous
#include <cuda_runtime.h>
#include <cuda_fp16.h>
#include <cstdint>

// ============================================================================
// GhostLinear: out[M,N] = X[M,K] @ W^T,  W[N,K] = lut[indices]*scale
// M=16384, N=4096, K=4096
// Toolchain: PTX target sm_103 (no 'a') -> no tcgen05.ld -> legacy mma.sync.
// R3: 1894us @ tensor=49.5% (1 CTA/SM, 16 warps). R4 (2x128-thread CTAs)
// regressed: same 16 warps/SM + more L2 traffic. R5: R3 shape + explicit
// double-buffered fragments to kill the LDSM->MMA WAR serialization.
// ============================================================================

#define M_TOTAL 16384
#define N_TOTAL 4096
#define K_TOTAL 4096
#define CODES   256

#define BM 128
#define BN 256
#define BK 64
#define STAGES 4
#define NITER (K_TOTAL / BK)             // 64

#define BKP 72                            // padded halves per smem row (144 B)
#define A_STAGE_HALFS (BM * BKP)          // 9216
#define B_STAGE_HALFS (BN * BKP)          // 18432
#define STAGE_HALFS (A_STAGE_HALFS + B_STAGE_HALFS)      // 27648
#define SMEM_BYTES (STAGES * STAGE_HALFS * 2)            // 221184

__device__ __align__(1024) __half g_X[(size_t)M_TOTAL * K_TOTAL];  // 128 MB
__device__ __align__(1024) __half g_W[(size_t)N_TOTAL * K_TOTAL];  //  32 MB

__device__ __forceinline__ uint32_t smem_u32(const void* p) {
    uint32_t a;
    asm("{ .reg .u64 t; cvta.to.shared.u64 t, %1; cvt.u32.u64 %0, t; }"
        : "=r"(a) : "l"(p));
    return a;
}

#define CP_ASYNC16(dst32, src) \
    asm volatile("cp.async.cg.shared.global [%0], [%1], 16;" \
                 :: "r"(dst32), "l"(src) : "memory")
#define CP_COMMIT() asm volatile("cp.async.commit_group;" ::: "memory")
#define CP_WAIT(n)  asm volatile("cp.async.wait_group %0;" :: "n"(n) : "memory")

#define LDSM4(r0, r1, r2, r3, addr) \
    asm volatile("ldmatrix.sync.aligned.m8n8.x4.shared.b16 {%0,%1,%2,%3}, [%4];" \
                 : "=r"(r0), "=r"(r1), "=r"(r2), "=r"(r3) : "r"(addr))

__device__ __forceinline__ void mma16816(float* c, const uint32_t* a, const uint32_t* b) {
    asm volatile(
        "mma.sync.aligned.m16n8k16.row.col.f32.f16.f16.f32 "
        "{%0,%1,%2,%3}, {%4,%5,%6,%7}, {%8,%9}, {%0,%1,%2,%3};"
        : "+f"(c[0]), "+f"(c[1]), "+f"(c[2]), "+f"(c[3])
        : "r"(a[0]), "r"(a[1]), "r"(a[2]), "r"(a[3]), "r"(b[0]), "r"(b[1]));
}

// ---------------------------------------------------------------------------
// Fused converter: blocks [0, XB) convert X fp32->fp16 (8/thread),
// blocks [XB, XB+WB) dequant W via codebook (4/thread).
// ---------------------------------------------------------------------------
#define XBLOCKS 32768
#define WBLOCKS 16384

__device__ __forceinline__ uint32_t h2u(__half2 h) {
    return *reinterpret_cast<uint32_t*>(&h);
}

__global__ void __launch_bounds__(256) convert_kernel(const float* __restrict__ x,
                                                      const int* __restrict__ idx,
                                                      const float* __restrict__ scale,
                                                      const float* __restrict__ lut) {
    if (blockIdx.x < XBLOCKS) {
        size_t i = ((size_t)blockIdx.x * 256 + threadIdx.x) * 8;
        float4 a = *reinterpret_cast<const float4*>(x + i);
        float4 b = *reinterpret_cast<const float4*>(x + i + 4);
        uint4 o;
        o.x = h2u(__floats2half2_rn(a.x, a.y));
        o.y = h2u(__floats2half2_rn(a.z, a.w));
        o.z = h2u(__floats2half2_rn(b.x, b.y));
        o.w = h2u(__floats2half2_rn(b.z, b.w));
        *reinterpret_cast<uint4*>(g_X + i) = o;
    } else {
        __shared__ float slut[CODES];
        if (threadIdx.x < CODES) slut[threadIdx.x] = lut[threadIdx.x];
        __syncthreads();
        size_t i = ((size_t)(blockIdx.x - XBLOCKS) * 256 + threadIdx.x) * 4;
        int4 v = *reinterpret_cast<const int4*>(idx + i);
        float s = scale[i >> 12];   // K_TOTAL elements per output row
        uint2 o;
        o.x = h2u(__floats2half2_rn(slut[v.x] * s, slut[v.y] * s));
        o.y = h2u(__floats2half2_rn(slut[v.z] * s, slut[v.w] * s));
        *reinterpret_cast<uint2*>(g_W + i) = o;
    }
}

// ---------------------------------------------------------------------------
// GEMM: CTA = 128(M) x 256(N), BK=64, 4-stage cp.async pipeline.
// 512 threads = 16 warps in 4(M) x 4(N); warp tile 32 x 64.
// Double-buffered fragments: LDSM for ks+1 overlaps MMAs of ks.
// ---------------------------------------------------------------------------
__global__ void __launch_bounds__(512, 1) gemm_kernel(const __half* __restrict__ X,
                                                      const __half* __restrict__ W,
                                                      float* __restrict__ out) {
    extern __shared__ __half sm[];
    const uint32_t smem_base = smem_u32(sm);
    const int tid  = threadIdx.x;
    const int lane = tid & 31;
    const int wid  = tid >> 5;
    const int warp_m = wid & 3;    // 32-row band
    const int warp_n = wid >> 2;   // 64-col band
    const int m_base = blockIdx.y * BM;
    const int n_base = blockIdx.x * BN;

    // --- cp.async mapping: per thread 2 A + 4 B chunks of 16B ---
    const int a0i = tid * 2, a1i = tid * 2 + 1;
    const int ar0 = a0i >> 3, ac0 = a0i & 7;
    const int ar1 = a1i >> 3, ac1 = a1i & 7;
    const __half* gA0 = X + (size_t)(m_base + ar0) * K_TOTAL + ac0 * 8;
    const __half* gA1 = X + (size_t)(m_base + ar1) * K_TOTAL + ac1 * 8;
    const uint32_t dA0 = (uint32_t)(ar0 * BKP + ac0 * 8) * 2;
    const uint32_t dA1 = (uint32_t)(ar1 * BKP + ac1 * 8) * 2;
    const __half* gB[4];
    uint32_t dB[4];
    #pragma unroll
    for (int q = 0; q < 4; q++) {
        int bi = tid * 4 + q;
        int br = bi >> 3, bc = bi & 7;
        gB[q] = W + (size_t)(n_base + br) * K_TOTAL + bc * 8;
        dB[q] = (uint32_t)(A_STAGE_HALFS + br * BKP + bc * 8) * 2;
    }

    // --- ldmatrix per-thread address components (byte offsets within stage) ---
    const uint32_t a_off0 = (uint32_t)((warp_m * 32 + (lane & 15)) * BKP
                                       + (lane >> 4) * 8) * 2;
    const uint32_t b_off0 = (uint32_t)(A_STAGE_HALFS * 2)
                          + (uint32_t)(((warp_n * 64 + (lane & 7) + ((lane >> 4) & 1) * 8)) * BKP
                                       + ((lane >> 3) & 1) * 8) * 2;

    float acc[2][8][4];
    #pragma unroll
    for (int t = 0; t < 2; t++)
        #pragma unroll
        for (int j = 0; j < 8; j++)
            #pragma unroll
            for (int e = 0; e < 4; e++) acc[t][j][e] = 0.f;

    // --- prologue: fill STAGES-1 stages ---
    #pragma unroll
    for (int s = 0; s < STAGES - 1; s++) {
        uint32_t sb = smem_base + (uint32_t)(s * STAGE_HALFS) * 2;
        int koff = s * BK;
        CP_ASYNC16(sb + dA0, gA0 + koff);
        CP_ASYNC16(sb + dA1, gA1 + koff);
        #pragma unroll
        for (int q = 0; q < 4; q++) CP_ASYNC16(sb + dB[q], gB[q] + koff);
        CP_COMMIT();
    }

    // --- main loop ---
    for (int kit = 0; kit < NITER; kit++) {
        CP_WAIT(STAGES - 2);
        __syncthreads();

        {   // prefetch stage kit + STAGES-1
            int pf = kit + STAGES - 1;
            if (pf < NITER) {
                uint32_t sb = smem_base + (uint32_t)((pf % STAGES) * STAGE_HALFS) * 2;
                int koff = pf * BK;
                CP_ASYNC16(sb + dA0, gA0 + koff);
                CP_ASYNC16(sb + dA1, gA1 + koff);
                #pragma unroll
                for (int q = 0; q < 4; q++) CP_ASYNC16(sb + dB[q], gB[q] + koff);
            }
            CP_COMMIT();
        }

        const uint32_t sb = smem_base + (uint32_t)((kit % STAGES) * STAGE_HALFS) * 2;
        const uint32_t aBase = sb + a_off0;
        const uint32_t bBase = sb + b_off0;

        // --- double-buffered fragment pipeline over 4 ks steps ---
        uint32_t a[2][2][4], b[2][8][2];

        // load ks=0 into buffer 0
        {
            LDSM4(a[0][0][0], a[0][0][1], a[0][0][2], a[0][0][3], aBase);
            LDSM4(a[0][1][0], a[0][1][1], a[0][1][2], a[0][1][3], aBase + 16 * BKP * 2);
            #pragma unroll
            for (int jj = 0; jj < 4; jj++) {
                uint32_t addr = bBase + (uint32_t)(jj * 16 * BKP) * 2;
                LDSM4(b[0][jj * 2][0], b[0][jj * 2][1],
                      b[0][jj * 2 + 1][0], b[0][jj * 2 + 1][1], addr);
            }
        }

        #pragma unroll
        for (int ks = 0; ks < 4; ks++) {
            const int cur = ks & 1, nxt = cur ^ 1;
            if (ks < 3) {   // load ks+1 into the other buffer
                const uint32_t colb = (uint32_t)((ks + 1) * 16) * 2;
                LDSM4(a[nxt][0][0], a[nxt][0][1], a[nxt][0][2], a[nxt][0][3],
                      aBase + colb);
                LDSM4(a[nxt][1][0], a[nxt][1][1], a[nxt][1][2], a[nxt][1][3],
                      aBase + 16 * BKP * 2 + colb);
                #pragma unroll
                for (int jj = 0; jj < 4; jj++) {
                    uint32_t addr = bBase + (uint32_t)(jj * 16 * BKP) * 2 + colb;
                    LDSM4(b[nxt][jj * 2][0], b[nxt][jj * 2][1],
                          b[nxt][jj * 2 + 1][0], b[nxt][jj * 2 + 1][1], addr);
                }
            }
            #pragma unroll
            for (int t = 0; t < 2; t++)
                #pragma unroll
                for (int j = 0; j < 8; j++)
                    mma16816(acc[t][j], a[cur][t], b[cur][j]);
        }
    }

    // --- epilogue ---
    #pragma unroll
    for (int t = 0; t < 2; t++) {
        int row = m_base + warp_m * 32 + t * 16 + (lane >> 2);
        #pragma unroll
        for (int j = 0; j < 8; j++) {
            int col = n_base + warp_n * 64 + j * 8 + (lane & 3) * 2;
            *reinterpret_cast<float2*>(out + (size_t)row * N_TOTAL + col) =
                make_float2(acc[t][j][0], acc[t][j][1]);
            *reinterpret_cast<float2*>(out + (size_t)(row + 8) * N_TOTAL + col) =
                make_float2(acc[t][j][2], acc[t][j][3]);
        }
    }
}

// ---------------------------------------------------------------------------
// Host launcher
// ---------------------------------------------------------------------------
extern "C" void kernel_launch(void* const* d_in, const int* in_sizes, int n_in,
                              void* d_out, int out_size) {
    (void)in_sizes; (void)n_in; (void)out_size;
    const float* x     = (const float*)d_in[0];
    const float* scale = (const float*)d_in[1];
    const float* lut   = (const float*)d_in[2];
    const int*   idx   = (const int*)d_in[3];
    float* out = (float*)d_out;

    void *pX = nullptr, *pW = nullptr;
    cudaGetSymbolAddress(&pX, g_X);
    cudaGetSymbolAddress(&pW, g_W);

    cudaFuncSetAttribute(gemm_kernel, cudaFuncAttributeMaxDynamicSharedMemorySize,
                         SMEM_BYTES);

    convert_kernel<<<XBLOCKS + WBLOCKS, 256>>>(x, idx, scale, lut);

    dim3 grid(N_TOTAL / BN, M_TOTAL / BM);   // (16, 128): x fastest -> A-band L2 reuse
    gemm_kernel<<<grid, 512, SMEM_BYTES>>>((const __half*)pX, (const __half*)pW, out);
}

// round 6
// speedup vs baseline: 1.3183x; 1.2548x over previous
#include <cuda_runtime.h>
#include <cuda_fp16.h>
#include <cstdint>

// ============================================================================
// GhostLinear: out[M,N] = X[M,K] @ W^T,  W[N,K] = lut[indices]*scale
// M=16384, N=4096, K=4096
// Toolchain: PTX target sm_103 (no 'a') -> no tcgen05.ld -> legacy mma.sync.
// R3 analysis: kit = 3912cyc ~= HMMA demand 2048 (rt~8/SMSP) + LDSM 1536,
// phases serialized by the per-kit barrier convoy. R6: 8 warps x 255 regs,
// warp tile 64x64, true double-buffered fragments -> overlap LDSM with MMA,
// and cut LDSM traffic 192->128 KB/kit.
// ============================================================================

#define M_TOTAL 16384
#define N_TOTAL 4096
#define K_TOTAL 4096
#define CODES   256

#define BM 128
#define BN 256
#define BK 64
#define STAGES 4
#define NITER (K_TOTAL / BK)             // 64

#define BKP 72                            // padded halves per smem row (144 B)
#define A_STAGE_HALFS (BM * BKP)          // 9216
#define B_STAGE_HALFS (BN * BKP)          // 18432
#define STAGE_HALFS (A_STAGE_HALFS + B_STAGE_HALFS)      // 27648
#define SMEM_BYTES (STAGES * STAGE_HALFS * 2)            // 221184

__device__ __align__(1024) __half g_X[(size_t)M_TOTAL * K_TOTAL];  // 128 MB
__device__ __align__(1024) __half g_W[(size_t)N_TOTAL * K_TOTAL];  //  32 MB

__device__ __forceinline__ uint32_t smem_u32(const void* p) {
    uint32_t a;
    asm("{ .reg .u64 t; cvta.to.shared.u64 t, %1; cvt.u32.u64 %0, t; }"
        : "=r"(a) : "l"(p));
    return a;
}

#define CP_ASYNC16(dst32, src) \
    asm volatile("cp.async.cg.shared.global [%0], [%1], 16;" \
                 :: "r"(dst32), "l"(src) : "memory")
#define CP_COMMIT() asm volatile("cp.async.commit_group;" ::: "memory")
#define CP_WAIT(n)  asm volatile("cp.async.wait_group %0;" :: "n"(n) : "memory")

#define LDSM4(r0, r1, r2, r3, addr) \
    asm volatile("ldmatrix.sync.aligned.m8n8.x4.shared.b16 {%0,%1,%2,%3}, [%4];" \
                 : "=r"(r0), "=r"(r1), "=r"(r2), "=r"(r3) : "r"(addr))

__device__ __forceinline__ void mma16816(float* c, const uint32_t* a, const uint32_t* b) {
    asm volatile(
        "mma.sync.aligned.m16n8k16.row.col.f32.f16.f16.f32 "
        "{%0,%1,%2,%3}, {%4,%5,%6,%7}, {%8,%9}, {%0,%1,%2,%3};"
        : "+f"(c[0]), "+f"(c[1]), "+f"(c[2]), "+f"(c[3])
        : "r"(a[0]), "r"(a[1]), "r"(a[2]), "r"(a[3]), "r"(b[0]), "r"(b[1]));
}

// ---------------------------------------------------------------------------
// Fused converter: blocks [0, XB) convert X fp32->fp16 (8/thread),
// blocks [XB, XB+WB) dequant W via codebook (4/thread).
// ---------------------------------------------------------------------------
#define XBLOCKS 32768
#define WBLOCKS 16384

__device__ __forceinline__ uint32_t h2u(__half2 h) {
    return *reinterpret_cast<uint32_t*>(&h);
}

__global__ void __launch_bounds__(256) convert_kernel(const float* __restrict__ x,
                                                      const int* __restrict__ idx,
                                                      const float* __restrict__ scale,
                                                      const float* __restrict__ lut) {
    if (blockIdx.x < XBLOCKS) {
        size_t i = ((size_t)blockIdx.x * 256 + threadIdx.x) * 8;
        float4 a = *reinterpret_cast<const float4*>(x + i);
        float4 b = *reinterpret_cast<const float4*>(x + i + 4);
        uint4 o;
        o.x = h2u(__floats2half2_rn(a.x, a.y));
        o.y = h2u(__floats2half2_rn(a.z, a.w));
        o.z = h2u(__floats2half2_rn(b.x, b.y));
        o.w = h2u(__floats2half2_rn(b.z, b.w));
        *reinterpret_cast<uint4*>(g_X + i) = o;
    } else {
        __shared__ float slut[CODES];
        if (threadIdx.x < CODES) slut[threadIdx.x] = lut[threadIdx.x];
        __syncthreads();
        size_t i = ((size_t)(blockIdx.x - XBLOCKS) * 256 + threadIdx.x) * 4;
        int4 v = *reinterpret_cast<const int4*>(idx + i);
        float s = scale[i >> 12];   // K_TOTAL elements per output row
        uint2 o;
        o.x = h2u(__floats2half2_rn(slut[v.x] * s, slut[v.y] * s));
        o.y = h2u(__floats2half2_rn(slut[v.z] * s, slut[v.w] * s));
        *reinterpret_cast<uint2*>(g_W + i) = o;
    }
}

// ---------------------------------------------------------------------------
// GEMM: CTA = 128(M) x 256(N), BK=64, 4-stage cp.async pipeline.
// 256 threads = 8 warps in 2(M) x 4(N); warp tile 64 x 64.
// acc = 128 regs/thread; double-buffered fragments (64 regs) overlap
// LDSM of ks+1 with the 32-MMA burst of ks.
// ---------------------------------------------------------------------------
__global__ void __launch_bounds__(256, 1) gemm_kernel(const __half* __restrict__ X,
                                                      const __half* __restrict__ W,
                                                      float* __restrict__ out) {
    extern __shared__ __half sm[];
    const uint32_t smem_base = smem_u32(sm);
    const int tid  = threadIdx.x;
    const int lane = tid & 31;
    const int wid  = tid >> 5;
    const int warp_m = wid & 1;    // 64-row band
    const int warp_n = wid >> 1;   // 64-col band (0..3)
    const int m_base = blockIdx.y * BM;
    const int n_base = blockIdx.x * BN;

    // --- cp.async mapping (register-lean, strided chunks) ---
    // chunk idx = tid + 256*k ; row = (tid>>3) + 32k ; colchunk = tid&7
    const int crow = tid >> 3, ccol = tid & 7;
    const __half* gA = X + (size_t)(m_base + crow) * K_TOTAL + ccol * 8;
    const __half* gB = W + (size_t)(n_base + crow) * K_TOTAL + ccol * 8;
    const uint32_t dA = (uint32_t)(crow * BKP + ccol * 8) * 2;
    const uint32_t dB = (uint32_t)(A_STAGE_HALFS + crow * BKP + ccol * 8) * 2;
    const size_t   gstep = (size_t)32 * K_TOTAL;       // 32 rows in gmem
    const uint32_t dstep = (uint32_t)(32 * BKP) * 2;   // 32 rows in smem

    // --- ldmatrix per-thread byte offsets within a stage ---
    const uint32_t a_off0 = (uint32_t)((warp_m * 64 + (lane & 15)) * BKP
                                       + (lane >> 4) * 8) * 2;
    const uint32_t b_off0 = (uint32_t)(A_STAGE_HALFS * 2)
        + (uint32_t)((warp_n * 64 + (lane & 7) + ((lane >> 4) & 1) * 8) * BKP
                     + ((lane >> 3) & 1) * 8) * 2;

    float acc[4][8][4];
    #pragma unroll
    for (int t = 0; t < 4; t++)
        #pragma unroll
        for (int j = 0; j < 8; j++)
            #pragma unroll
            for (int e = 0; e < 4; e++) acc[t][j][e] = 0.f;

    // --- prologue: fill STAGES-1 stages (4 A + 8 B chunks per thread) ---
    #pragma unroll
    for (int s = 0; s < STAGES - 1; s++) {
        uint32_t sb = smem_base + (uint32_t)(s * STAGE_HALFS) * 2;
        int koff = s * BK;
        #pragma unroll
        for (int q = 0; q < 4; q++) CP_ASYNC16(sb + dA + q * dstep, gA + koff + q * gstep);
        #pragma unroll
        for (int q = 0; q < 8; q++) CP_ASYNC16(sb + dB + q * dstep, gB + koff + q * gstep);
        CP_COMMIT();
    }

    // --- main loop ---
    for (int kit = 0; kit < NITER; kit++) {
        CP_WAIT(STAGES - 2);
        __syncthreads();

        {   // prefetch stage kit + STAGES-1
            int pf = kit + STAGES - 1;
            if (pf < NITER) {
                uint32_t sb = smem_base + (uint32_t)((pf % STAGES) * STAGE_HALFS) * 2;
                int koff = pf * BK;
                #pragma unroll
                for (int q = 0; q < 4; q++) CP_ASYNC16(sb + dA + q * dstep, gA + koff + q * gstep);
                #pragma unroll
                for (int q = 0; q < 8; q++) CP_ASYNC16(sb + dB + q * dstep, gB + koff + q * gstep);
            }
            CP_COMMIT();
        }

        const uint32_t sb = smem_base + (uint32_t)((kit % STAGES) * STAGE_HALFS) * 2;
        const uint32_t aBase = sb + a_off0;
        const uint32_t bBase = sb + b_off0;

        // --- fragment double buffer over 4 ks steps ---
        uint32_t a[2][4][4], b[2][8][2];

        // load ks=0 into buffer 0
        #pragma unroll
        for (int t = 0; t < 4; t++)
            LDSM4(a[0][t][0], a[0][t][1], a[0][t][2], a[0][t][3],
                  aBase + (uint32_t)(t * 16 * BKP) * 2);
        #pragma unroll
        for (int jj = 0; jj < 4; jj++)
            LDSM4(b[0][jj * 2][0], b[0][jj * 2][1],
                  b[0][jj * 2 + 1][0], b[0][jj * 2 + 1][1],
                  bBase + (uint32_t)(jj * 16 * BKP) * 2);

        #pragma unroll
        for (int ks = 0; ks < 4; ks++) {
            const int cur = ks & 1, nxt = cur ^ 1;
            if (ks < 3) {   // load ks+1 into the other buffer (overlaps MMAs)
                const uint32_t colb = (uint32_t)((ks + 1) * 16) * 2;
                #pragma unroll
                for (int t = 0; t < 4; t++)
                    LDSM4(a[nxt][t][0], a[nxt][t][1], a[nxt][t][2], a[nxt][t][3],
                          aBase + (uint32_t)(t * 16 * BKP) * 2 + colb);
                #pragma unroll
                for (int jj = 0; jj < 4; jj++)
                    LDSM4(b[nxt][jj * 2][0], b[nxt][jj * 2][1],
                          b[nxt][jj * 2 + 1][0], b[nxt][jj * 2 + 1][1],
                          bBase + (uint32_t)(jj * 16 * BKP) * 2 + colb);
            }
            #pragma unroll
            for (int t = 0; t < 4; t++)
                #pragma unroll
                for (int j = 0; j < 8; j++)
                    mma16816(acc[t][j], a[cur][t], b[cur][j]);
        }
    }

    // --- epilogue ---
    #pragma unroll
    for (int t = 0; t < 4; t++) {
        int row = m_base + warp_m * 64 + t * 16 + (lane >> 2);
        #pragma unroll
        for (int j = 0; j < 8; j++) {
            int col = n_base + warp_n * 64 + j * 8 + (lane & 3) * 2;
            *reinterpret_cast<float2*>(out + (size_t)row * N_TOTAL + col) =
                make_float2(acc[t][j][0], acc[t][j][1]);
            *reinterpret_cast<float2*>(out + (size_t)(row + 8) * N_TOTAL + col) =
                make_float2(acc[t][j][2], acc[t][j][3]);
        }
    }
}

// ---------------------------------------------------------------------------
// Host launcher
// ---------------------------------------------------------------------------
extern "C" void kernel_launch(void* const* d_in, const int* in_sizes, int n_in,
                              void* d_out, int out_size) {
    (void)in_sizes; (void)n_in; (void)out_size;
    const float* x     = (const float*)d_in[0];
    const float* scale = (const float*)d_in[1];
    const float* lut   = (const float*)d_in[2];
    const int*   idx   = (const int*)d_in[3];
    float* out = (float*)d_out;

    void *pX = nullptr, *pW = nullptr;
    cudaGetSymbolAddress(&pX, g_X);
    cudaGetSymbolAddress(&pW, g_W);

    cudaFuncSetAttribute(gemm_kernel, cudaFuncAttributeMaxDynamicSharedMemorySize,
                         SMEM_BYTES);

    convert_kernel<<<XBLOCKS + WBLOCKS, 256>>>(x, idx, scale, lut);

    dim3 grid(N_TOTAL / BN, M_TOTAL / BM);   // (16, 128): x fastest -> A-band L2 reuse
    gemm_kernel<<<grid, 256, SMEM_BYTES>>>((const __half*)pX, (const __half*)pW, out);
}

// round 8
// speedup vs baseline: 1.6591x; 1.2586x over previous
#include <cuda_runtime.h>
#include <cuda_fp16.h>
#include <cstdint>

// ============================================================================
// GhostLinear: out[M,N] = X[M,K] @ W^T,  W[N,K] = lut[indices]*scale
// M=16384, N=4096, K=4096
// Toolchain: PTX target sm_103 (no 'a') -> no tcgen05.ld -> legacy mma.sync.
// R6: 1613us, tensor=58.6%. R7 (cross-kit frag pipeline) FAILED: read other
// threads' cp.async data after only a per-thread wait_group (no barrier).
// R8 = R7 with the sync fixed: at ks3, CP_WAIT -> __syncthreads -> cross-kit
// LDSM. One barrier per kit; ks3 MMAs (cur buffer) have no dependence on the
// post-barrier loads, so the crossbar work stays overlapped with MMA issue.
// ============================================================================

#define M_TOTAL 16384
#define N_TOTAL 4096
#define K_TOTAL 4096
#define CODES   256

#define BM 128
#define BN 256
#define BK 64
#define STAGES 4
#define NITER (K_TOTAL / BK)             // 64

#define BKP 72                            // padded halves per smem row (144 B)
#define A_STAGE_HALFS (BM * BKP)          // 9216
#define B_STAGE_HALFS (BN * BKP)          // 18432
#define STAGE_HALFS (A_STAGE_HALFS + B_STAGE_HALFS)      // 27648
#define SMEM_BYTES (STAGES * STAGE_HALFS * 2)            // 221184

__device__ __align__(1024) __half g_X[(size_t)M_TOTAL * K_TOTAL];  // 128 MB
__device__ __align__(1024) __half g_W[(size_t)N_TOTAL * K_TOTAL];  //  32 MB

__device__ __forceinline__ uint32_t smem_u32(const void* p) {
    uint32_t a;
    asm("{ .reg .u64 t; cvta.to.shared.u64 t, %1; cvt.u32.u64 %0, t; }"
        : "=r"(a) : "l"(p));
    return a;
}

#define CP_ASYNC16(dst32, src) \
    asm volatile("cp.async.cg.shared.global [%0], [%1], 16;" \
                 :: "r"(dst32), "l"(src) : "memory")
#define CP_COMMIT() asm volatile("cp.async.commit_group;" ::: "memory")
#define CP_WAIT(n)  asm volatile("cp.async.wait_group %0;" :: "n"(n) : "memory")

#define LDSM4(r0, r1, r2, r3, addr) \
    asm volatile("ldmatrix.sync.aligned.m8n8.x4.shared.b16 {%0,%1,%2,%3}, [%4];" \
                 : "=r"(r0), "=r"(r1), "=r"(r2), "=r"(r3) : "r"(addr))

__device__ __forceinline__ void mma16816(float* c, const uint32_t* a, const uint32_t* b) {
    asm volatile(
        "mma.sync.aligned.m16n8k16.row.col.f32.f16.f16.f32 "
        "{%0,%1,%2,%3}, {%4,%5,%6,%7}, {%8,%9}, {%0,%1,%2,%3};"
        : "+f"(c[0]), "+f"(c[1]), "+f"(c[2]), "+f"(c[3])
        : "r"(a[0]), "r"(a[1]), "r"(a[2]), "r"(a[3]), "r"(b[0]), "r"(b[1]));
}

// ---------------------------------------------------------------------------
// Fused converter: blocks [0, XB) convert X fp32->fp16 (8/thread),
// blocks [XB, XB+WB) dequant W via codebook (4/thread).
// ---------------------------------------------------------------------------
#define XBLOCKS 32768
#define WBLOCKS 16384

__device__ __forceinline__ uint32_t h2u(__half2 h) {
    return *reinterpret_cast<uint32_t*>(&h);
}

__global__ void __launch_bounds__(256) convert_kernel(const float* __restrict__ x,
                                                      const int* __restrict__ idx,
                                                      const float* __restrict__ scale,
                                                      const float* __restrict__ lut) {
    if (blockIdx.x < XBLOCKS) {
        size_t i = ((size_t)blockIdx.x * 256 + threadIdx.x) * 8;
        float4 a = *reinterpret_cast<const float4*>(x + i);
        float4 b = *reinterpret_cast<const float4*>(x + i + 4);
        uint4 o;
        o.x = h2u(__floats2half2_rn(a.x, a.y));
        o.y = h2u(__floats2half2_rn(a.z, a.w));
        o.z = h2u(__floats2half2_rn(b.x, b.y));
        o.w = h2u(__floats2half2_rn(b.z, b.w));
        *reinterpret_cast<uint4*>(g_X + i) = o;
    } else {
        __shared__ float slut[CODES];
        if (threadIdx.x < CODES) slut[threadIdx.x] = lut[threadIdx.x];
        __syncthreads();
        size_t i = ((size_t)(blockIdx.x - XBLOCKS) * 256 + threadIdx.x) * 4;
        int4 v = *reinterpret_cast<const int4*>(idx + i);
        float s = scale[i >> 12];   // K_TOTAL elements per output row
        uint2 o;
        o.x = h2u(__floats2half2_rn(slut[v.x] * s, slut[v.y] * s));
        o.y = h2u(__floats2half2_rn(slut[v.z] * s, slut[v.w] * s));
        *reinterpret_cast<uint2*>(g_W + i) = o;
    }
}

// ---------------------------------------------------------------------------
// GEMM: CTA = 128(M) x 256(N), BK=64, 4-stage cp.async pipeline.
// 256 threads = 8 warps in 2(M) x 4(N); warp tile 64 x 64.
// Fragment double-buffer pipelined across kit boundaries (sync-correct).
// ---------------------------------------------------------------------------
__global__ void __launch_bounds__(256, 1) gemm_kernel(const __half* __restrict__ X,
                                                      const __half* __restrict__ W,
                                                      float* __restrict__ out) {
    extern __shared__ __half sm[];
    const uint32_t smem_base = smem_u32(sm);
    const int tid  = threadIdx.x;
    const int lane = tid & 31;
    const int wid  = tid >> 5;
    const int warp_m = wid & 1;    // 64-row band
    const int warp_n = wid >> 1;   // 64-col band (0..3)
    const int m_base = blockIdx.y * BM;
    const int n_base = blockIdx.x * BN;

    // --- cp.async mapping (register-lean, strided chunks) ---
    const int crow = tid >> 3, ccol = tid & 7;
    const __half* gA = X + (size_t)(m_base + crow) * K_TOTAL + ccol * 8;
    const __half* gB = W + (size_t)(n_base + crow) * K_TOTAL + ccol * 8;
    const uint32_t dA = (uint32_t)(crow * BKP + ccol * 8) * 2;
    const uint32_t dB = (uint32_t)(A_STAGE_HALFS + crow * BKP + ccol * 8) * 2;
    const size_t   gstep = (size_t)32 * K_TOTAL;       // 32 rows in gmem
    const uint32_t dstep = (uint32_t)(32 * BKP) * 2;   // 32 rows in smem

    // --- ldmatrix per-thread byte offsets within a stage ---
    const uint32_t a_off0 = (uint32_t)((warp_m * 64 + (lane & 15)) * BKP
                                       + (lane >> 4) * 8) * 2;
    const uint32_t b_off0 = (uint32_t)(A_STAGE_HALFS * 2)
        + (uint32_t)((warp_n * 64 + (lane & 7) + ((lane >> 4) & 1) * 8) * BKP
                     + ((lane >> 3) & 1) * 8) * 2;

    float acc[4][8][4];
    #pragma unroll
    for (int t = 0; t < 4; t++)
        #pragma unroll
        for (int j = 0; j < 8; j++)
            #pragma unroll
            for (int e = 0; e < 4; e++) acc[t][j][e] = 0.f;

    uint32_t a[2][4][4], b[2][8][2];

    // fragment loader: buffer bf <- (stage base sb, k16 column colk)
    #define LOAD_FRAGS(bf, sb, colk) do {                                      \
        const uint32_t _aB = (sb) + a_off0 + (uint32_t)((colk) * 16 * 2);      \
        const uint32_t _bB = (sb) + b_off0 + (uint32_t)((colk) * 16 * 2);      \
        _Pragma("unroll")                                                      \
        for (int _t = 0; _t < 4; _t++)                                         \
            LDSM4(a[bf][_t][0], a[bf][_t][1], a[bf][_t][2], a[bf][_t][3],      \
                  _aB + (uint32_t)(_t * 16 * BKP) * 2);                        \
        _Pragma("unroll")                                                      \
        for (int _jj = 0; _jj < 4; _jj++)                                      \
            LDSM4(b[bf][_jj * 2][0], b[bf][_jj * 2][1],                        \
                  b[bf][_jj * 2 + 1][0], b[bf][_jj * 2 + 1][1],                \
                  _bB + (uint32_t)(_jj * 16 * BKP) * 2);                       \
    } while (0)

    // --- prologue: fill STAGES-1 stages ---
    #pragma unroll
    for (int s = 0; s < STAGES - 1; s++) {
        uint32_t sb = smem_base + (uint32_t)(s * STAGE_HALFS) * 2;
        int koff = s * BK;
        #pragma unroll
        for (int q = 0; q < 4; q++) CP_ASYNC16(sb + dA + q * dstep, gA + koff + q * gstep);
        #pragma unroll
        for (int q = 0; q < 8; q++) CP_ASYNC16(sb + dB + q * dstep, gB + koff + q * gstep);
        CP_COMMIT();
    }

    CP_WAIT(STAGES - 2);          // stage 0 resident (this thread)
    __syncthreads();              // ... and all threads -> fully visible
    LOAD_FRAGS(0, smem_base, 0);  // frag(kit=0, ks=0) -> buffer 0

    // --- main loop: one barrier per kit (at ks3), no exposed frag prologue ---
    for (int kit = 0; kit < NITER; kit++) {
        {   // prefetch stage kit + STAGES-1 into slot (kit+STAGES-1)%STAGES.
            // That slot's last reads (frag loads of kit-1, ks<=2) precede
            // kit-1's ks3 barrier -> safe to overwrite.
            int pf = kit + STAGES - 1;
            if (pf < NITER) {
                uint32_t sb = smem_base + (uint32_t)((pf % STAGES) * STAGE_HALFS) * 2;
                int koff = pf * BK;
                #pragma unroll
                for (int q = 0; q < 4; q++) CP_ASYNC16(sb + dA + q * dstep, gA + koff + q * gstep);
                #pragma unroll
                for (int q = 0; q < 8; q++) CP_ASYNC16(sb + dB + q * dstep, gB + koff + q * gstep);
            }
            CP_COMMIT();
        }

        const uint32_t sb = smem_base + (uint32_t)((kit % STAGES) * STAGE_HALFS) * 2;

        #pragma unroll
        for (int ks = 0; ks < 4; ks++) {
            const int cur = ks & 1, nxt = cur ^ 1;
            if (ks < 3) {
                // next ks of this kit (stage already resident)
                LOAD_FRAGS(nxt, sb, ks + 1);
            } else if (kit < NITER - 1) {
                // cross-kit: all threads prove stage kit+1 resident, THEN read.
                CP_WAIT(STAGES - 2);
                __syncthreads();
                const uint32_t sb2 = smem_base
                    + (uint32_t)(((kit + 1) % STAGES) * STAGE_HALFS) * 2;
                LOAD_FRAGS(nxt, sb2, 0);
            }
            #pragma unroll
            for (int t = 0; t < 4; t++)
                #pragma unroll
                for (int j = 0; j < 8; j++)
                    mma16816(acc[t][j], a[cur][t], b[cur][j]);
        }
    }

    // --- epilogue ---
    #pragma unroll
    for (int t = 0; t < 4; t++) {
        int row = m_base + warp_m * 64 + t * 16 + (lane >> 2);
        #pragma unroll
        for (int j = 0; j < 8; j++) {
            int col = n_base + warp_n * 64 + j * 8 + (lane & 3) * 2;
            *reinterpret_cast<float2*>(out + (size_t)row * N_TOTAL + col) =
                make_float2(acc[t][j][0], acc[t][j][1]);
            *reinterpret_cast<float2*>(out + (size_t)(row + 8) * N_TOTAL + col) =
                make_float2(acc[t][j][2], acc[t][j][3]);
        }
    }
    #undef LOAD_FRAGS
}

// ---------------------------------------------------------------------------
// Host launcher
// ---------------------------------------------------------------------------
extern "C" void kernel_launch(void* const* d_in, const int* in_sizes, int n_in,
                              void* d_out, int out_size) {
    (void)in_sizes; (void)n_in; (void)out_size;
    const float* x     = (const float*)d_in[0];
    const float* scale = (const float*)d_in[1];
    const float* lut   = (const float*)d_in[2];
    const int*   idx   = (const int*)d_in[3];
    float* out = (float*)d_out;

    void *pX = nullptr, *pW = nullptr;
    cudaGetSymbolAddress(&pX, g_X);
    cudaGetSymbolAddress(&pW, g_W);

    cudaFuncSetAttribute(gemm_kernel, cudaFuncAttributeMaxDynamicSharedMemorySize,
                         SMEM_BYTES);

    convert_kernel<<<XBLOCKS + WBLOCKS, 256>>>(x, idx, scale, lut);

    dim3 grid(N_TOTAL / BN, M_TOTAL / BM);   // (16, 128): x fastest -> A-band L2 reuse
    gemm_kernel<<<grid, 256, SMEM_BYTES>>>((const __half*)pX, (const __half*)pW, out);
}

// round 9
// speedup vs baseline: 1.7487x; 1.0540x over previous
#include <cuda_runtime.h>
#include <cuda_fp16.h>
#include <cstdint>

// ============================================================================
// GhostLinear: out[M,N] = X[M,K] @ W^T,  W[N,K] = lut[indices]*scale
// M=16384, N=4096, K=4096
// Toolchain: PTX target sm_103 (no 'a') -> no tcgen05.ld -> legacy mma.sync
// (HMMA rt~8/SMSP => GEMM floor ~0.96ms). R8: 1282us, tensor=74.8%.
// R9: BK=128 / 2 stages (32 kits: half the barriers) + cp.async issues
// interleaved across ks0-3 so the tensor pipe never drains behind an
// LDGSTS burst. Commit at ks3 -> ks7 CP_WAIT(0) has ~2000cyc cover.
// ============================================================================

#define M_TOTAL 16384
#define N_TOTAL 4096
#define K_TOTAL 4096
#define CODES   256

#define BM 128
#define BN 256
#define BK 128
#define STAGES 2
#define NITER (K_TOTAL / BK)             // 32
#define KS_PER_KIT 8                      // eight k16 steps

#define BKP 136                           // padded halves per smem row (272 B)
#define A_STAGE_HALFS (BM * BKP)          // 17408
#define B_STAGE_HALFS (BN * BKP)          // 34816
#define STAGE_HALFS (A_STAGE_HALFS + B_STAGE_HALFS)      // 52224
#define SMEM_BYTES (STAGES * STAGE_HALFS * 2)            // 208896

__device__ __align__(1024) __half g_X[(size_t)M_TOTAL * K_TOTAL];  // 128 MB
__device__ __align__(1024) __half g_W[(size_t)N_TOTAL * K_TOTAL];  //  32 MB

__device__ __forceinline__ uint32_t smem_u32(const void* p) {
    uint32_t a;
    asm("{ .reg .u64 t; cvta.to.shared.u64 t, %1; cvt.u32.u64 %0, t; }"
        : "=r"(a) : "l"(p));
    return a;
}

#define CP_ASYNC16(dst32, src) \
    asm volatile("cp.async.cg.shared.global [%0], [%1], 16;" \
                 :: "r"(dst32), "l"(src) : "memory")
#define CP_COMMIT() asm volatile("cp.async.commit_group;" ::: "memory")
#define CP_WAIT(n)  asm volatile("cp.async.wait_group %0;" :: "n"(n) : "memory")

#define LDSM4(r0, r1, r2, r3, addr) \
    asm volatile("ldmatrix.sync.aligned.m8n8.x4.shared.b16 {%0,%1,%2,%3}, [%4];" \
                 : "=r"(r0), "=r"(r1), "=r"(r2), "=r"(r3) : "r"(addr))

__device__ __forceinline__ void mma16816(float* c, const uint32_t* a, const uint32_t* b) {
    asm volatile(
        "mma.sync.aligned.m16n8k16.row.col.f32.f16.f16.f32 "
        "{%0,%1,%2,%3}, {%4,%5,%6,%7}, {%8,%9}, {%0,%1,%2,%3};"
        : "+f"(c[0]), "+f"(c[1]), "+f"(c[2]), "+f"(c[3])
        : "r"(a[0]), "r"(a[1]), "r"(a[2]), "r"(a[3]), "r"(b[0]), "r"(b[1]));
}

// ---------------------------------------------------------------------------
// Fused converter: blocks [0, XB) convert X fp32->fp16 (8/thread),
// blocks [XB, XB+WB) dequant W via codebook (4/thread).
// ---------------------------------------------------------------------------
#define XBLOCKS 32768
#define WBLOCKS 16384

__device__ __forceinline__ uint32_t h2u(__half2 h) {
    return *reinterpret_cast<uint32_t*>(&h);
}

__global__ void __launch_bounds__(256) convert_kernel(const float* __restrict__ x,
                                                      const int* __restrict__ idx,
                                                      const float* __restrict__ scale,
                                                      const float* __restrict__ lut) {
    if (blockIdx.x < XBLOCKS) {
        size_t i = ((size_t)blockIdx.x * 256 + threadIdx.x) * 8;
        float4 a = *reinterpret_cast<const float4*>(x + i);
        float4 b = *reinterpret_cast<const float4*>(x + i + 4);
        uint4 o;
        o.x = h2u(__floats2half2_rn(a.x, a.y));
        o.y = h2u(__floats2half2_rn(a.z, a.w));
        o.z = h2u(__floats2half2_rn(b.x, b.y));
        o.w = h2u(__floats2half2_rn(b.z, b.w));
        *reinterpret_cast<uint4*>(g_X + i) = o;
    } else {
        __shared__ float slut[CODES];
        if (threadIdx.x < CODES) slut[threadIdx.x] = lut[threadIdx.x];
        __syncthreads();
        size_t i = ((size_t)(blockIdx.x - XBLOCKS) * 256 + threadIdx.x) * 4;
        int4 v = *reinterpret_cast<const int4*>(idx + i);
        float s = scale[i >> 12];   // K_TOTAL elements per output row
        uint2 o;
        o.x = h2u(__floats2half2_rn(slut[v.x] * s, slut[v.y] * s));
        o.y = h2u(__floats2half2_rn(slut[v.z] * s, slut[v.w] * s));
        *reinterpret_cast<uint2*>(g_W + i) = o;
    }
}

// ---------------------------------------------------------------------------
// GEMM: CTA = 128(M) x 256(N), BK=128, 2-stage cp.async pipeline.
// 256 threads = 8 warps in 2(M) x 4(N); warp tile 64 x 64.
// Fragment double-buffer pipelined across kit boundaries; cp.async issues
// spread over ks0-3.
// ---------------------------------------------------------------------------
__global__ void __launch_bounds__(256, 1) gemm_kernel(const __half* __restrict__ X,
                                                      const __half* __restrict__ W,
                                                      float* __restrict__ out) {
    extern __shared__ __half sm[];
    const uint32_t smem_base = smem_u32(sm);
    const int tid  = threadIdx.x;
    const int lane = tid & 31;
    const int wid  = tid >> 5;
    const int warp_m = wid & 1;    // 64-row band
    const int warp_n = wid >> 1;   // 64-col band (0..3)
    const int m_base = blockIdx.y * BM;
    const int n_base = blockIdx.x * BN;

    // --- cp.async mapping ---
    // Stage row layout: 16 chunks of 16B per row (BK=128 halves = 256B).
    // chunk i = tid + 256*q -> row = (tid>>4) + 16q, colchunk = tid&15.
    // A: q = 0..7 (128 rows), B: q = 0..15 (256 rows).
    const int crow = tid >> 4, ccol = tid & 15;
    const __half* gA = X + (size_t)(m_base + crow) * K_TOTAL + ccol * 8;
    const __half* gB = W + (size_t)(n_base + crow) * K_TOTAL + ccol * 8;
    const uint32_t dA = (uint32_t)(crow * BKP + ccol * 8) * 2;
    const uint32_t dB = (uint32_t)(A_STAGE_HALFS + crow * BKP + ccol * 8) * 2;
    const size_t   gstep = (size_t)16 * K_TOTAL;       // 16 rows in gmem
    const uint32_t dstep = (uint32_t)(16 * BKP) * 2;   // 16 rows in smem

    // --- ldmatrix per-thread byte offsets within a stage ---
    const uint32_t a_off0 = (uint32_t)((warp_m * 64 + (lane & 15)) * BKP
                                       + (lane >> 4) * 8) * 2;
    const uint32_t b_off0 = (uint32_t)(A_STAGE_HALFS * 2)
        + (uint32_t)((warp_n * 64 + (lane & 7) + ((lane >> 4) & 1) * 8) * BKP
                     + ((lane >> 3) & 1) * 8) * 2;

    float acc[4][8][4];
    #pragma unroll
    for (int t = 0; t < 4; t++)
        #pragma unroll
        for (int j = 0; j < 8; j++)
            #pragma unroll
            for (int e = 0; e < 4; e++) acc[t][j][e] = 0.f;

    uint32_t a[2][4][4], b[2][8][2];

    // fragment loader: buffer bf <- (stage base sb, k16 column colk)
    #define LOAD_FRAGS(bf, sb, colk) do {                                      \
        const uint32_t _aB = (sb) + a_off0 + (uint32_t)((colk) * 16 * 2);      \
        const uint32_t _bB = (sb) + b_off0 + (uint32_t)((colk) * 16 * 2);      \
        _Pragma("unroll")                                                      \
        for (int _t = 0; _t < 4; _t++)                                         \
            LDSM4(a[bf][_t][0], a[bf][_t][1], a[bf][_t][2], a[bf][_t][3],      \
                  _aB + (uint32_t)(_t * 16 * BKP) * 2);                        \
        _Pragma("unroll")                                                      \
        for (int _jj = 0; _jj < 4; _jj++)                                      \
            LDSM4(b[bf][_jj * 2][0], b[bf][_jj * 2][1],                        \
                  b[bf][_jj * 2 + 1][0], b[bf][_jj * 2 + 1][1],                \
                  _bB + (uint32_t)(_jj * 16 * BKP) * 2);                       \
    } while (0)

    // --- prologue: fill stage 0, make fully visible, load first fragments ---
    {
        int koff = 0;
        #pragma unroll
        for (int q = 0; q < 8; q++)  CP_ASYNC16(smem_base + dA + q * dstep, gA + koff + q * gstep);
        #pragma unroll
        for (int q = 0; q < 16; q++) CP_ASYNC16(smem_base + dB + q * dstep, gB + koff + q * gstep);
        CP_COMMIT();
    }
    CP_WAIT(0);
    __syncthreads();
    LOAD_FRAGS(0, smem_base, 0);

    // --- main loop: 32 kits, one barrier per kit (at ks7) ---
    for (int kit = 0; kit < NITER; kit++) {
        const uint32_t sb  = smem_base + (uint32_t)((kit & 1) * STAGE_HALFS) * 2;
        const uint32_t sb2 = smem_base + (uint32_t)(((kit + 1) & 1) * STAGE_HALFS) * 2;
        const __half* pA = gA + (size_t)(kit + 1) * BK;
        const __half* pB = gB + (size_t)(kit + 1) * BK;
        const bool has_next = (kit + 1 < NITER);

        #pragma unroll
        for (int ks = 0; ks < KS_PER_KIT; ks++) {
            const int cur = ks & 1, nxt = cur ^ 1;

            // spread next-stage cp.async issues over ks0..ks3 (6 per step)
            if (ks < 4 && has_next) {
                #pragma unroll
                for (int u = 0; u < 2; u++) {   // A chunks q = 2*ks+u
                    int q = 2 * ks + u;
                    CP_ASYNC16(sb2 + dA + q * dstep, pA + q * gstep);
                }
                #pragma unroll
                for (int u = 0; u < 4; u++) {   // B chunks q = 4*ks+u
                    int q = 4 * ks + u;
                    CP_ASYNC16(sb2 + dB + q * dstep, pB + q * gstep);
                }
                if (ks == 3) CP_COMMIT();
            }

            if (ks < KS_PER_KIT - 1) {
                LOAD_FRAGS(nxt, sb, ks + 1);
            } else if (has_next) {
                // all threads prove stage kit+1 resident, then read it
                CP_WAIT(0);
                __syncthreads();
                LOAD_FRAGS(nxt, sb2, 0);
            }

            #pragma unroll
            for (int t = 0; t < 4; t++)
                #pragma unroll
                for (int j = 0; j < 8; j++)
                    mma16816(acc[t][j], a[cur][t], b[cur][j]);
        }
    }

    // --- epilogue ---
    #pragma unroll
    for (int t = 0; t < 4; t++) {
        int row = m_base + warp_m * 64 + t * 16 + (lane >> 2);
        #pragma unroll
        for (int j = 0; j < 8; j++) {
            int col = n_base + warp_n * 64 + j * 8 + (lane & 3) * 2;
            *reinterpret_cast<float2*>(out + (size_t)row * N_TOTAL + col) =
                make_float2(acc[t][j][0], acc[t][j][1]);
            *reinterpret_cast<float2*>(out + (size_t)(row + 8) * N_TOTAL + col) =
                make_float2(acc[t][j][2], acc[t][j][3]);
        }
    }
    #undef LOAD_FRAGS
}

// ---------------------------------------------------------------------------
// Host launcher
// ---------------------------------------------------------------------------
extern "C" void kernel_launch(void* const* d_in, const int* in_sizes, int n_in,
                              void* d_out, int out_size) {
    (void)in_sizes; (void)n_in; (void)out_size;
    const float* x     = (const float*)d_in[0];
    const float* scale = (const float*)d_in[1];
    const float* lut   = (const float*)d_in[2];
    const int*   idx   = (const int*)d_in[3];
    float* out = (float*)d_out;

    void *pX = nullptr, *pW = nullptr;
    cudaGetSymbolAddress(&pX, g_X);
    cudaGetSymbolAddress(&pW, g_W);

    cudaFuncSetAttribute(gemm_kernel, cudaFuncAttributeMaxDynamicSharedMemorySize,
                         SMEM_BYTES);

    convert_kernel<<<XBLOCKS + WBLOCKS, 256>>>(x, idx, scale, lut);

    dim3 grid(N_TOTAL / BN, M_TOTAL / BM);   // (16, 128): x fastest -> A-band L2 reuse
    gemm_kernel<<<grid, 256, SMEM_BYTES>>>((const __half*)pX, (const __half*)pW, out);
}

// round 10
// speedup vs baseline: 1.7688x; 1.0115x over previous
#include <cuda_runtime.h>
#include <cuda_fp16.h>
#include <cstdint>

// ============================================================================
// GhostLinear: out[M,N] = X[M,K] @ W^T,  W[N,K] = lut[indices]*scale
// M=16384, N=4096, K=4096
// Toolchain: PTX target sm_103 (no 'a') -> no tcgen05.ld -> legacy mma.sync
// (HMMA rt~8/SMSP => GEMM floor ~0.96ms).
// R9: 1216us, tensor=79.3%. R10: persistent CTAs (grid=148); the cross-kit
// fragment/copy pipeline splices across TILE boundaries too, so stage fill
// of tile t+1 overlaps the epilogue of tile t. Output stores use .cs to keep
// W resident in L2.
// ============================================================================

#define M_TOTAL 16384
#define N_TOTAL 4096
#define K_TOTAL 4096
#define CODES   256

#define BM 128
#define BN 256
#define BK 128
#define NITER (K_TOTAL / BK)             // 32 kits
#define KS_PER_KIT 8                      // eight k16 steps per kit

#define NTILES ((M_TOTAL / BM) * (N_TOTAL / BN))   // 128 * 16 = 2048
#define NTX (N_TOTAL / BN)                          // 16 (n fastest)
#define GRID 148

#define BKP 136                           // padded halves per smem row (272 B)
#define A_STAGE_HALFS (BM * BKP)          // 17408
#define B_STAGE_HALFS (BN * BKP)          // 34816
#define STAGE_HALFS (A_STAGE_HALFS + B_STAGE_HALFS)      // 52224
#define SMEM_BYTES (2 * STAGE_HALFS * 2)                 // 208896

__device__ __align__(1024) __half g_X[(size_t)M_TOTAL * K_TOTAL];  // 128 MB
__device__ __align__(1024) __half g_W[(size_t)N_TOTAL * K_TOTAL];  //  32 MB

__device__ __forceinline__ uint32_t smem_u32(const void* p) {
    uint32_t a;
    asm("{ .reg .u64 t; cvta.to.shared.u64 t, %1; cvt.u32.u64 %0, t; }"
        : "=r"(a) : "l"(p));
    return a;
}

#define CP_ASYNC16(dst32, src) \
    asm volatile("cp.async.cg.shared.global [%0], [%1], 16;" \
                 :: "r"(dst32), "l"(src) : "memory")
#define CP_COMMIT() asm volatile("cp.async.commit_group;" ::: "memory")
#define CP_WAIT(n)  asm volatile("cp.async.wait_group %0;" :: "n"(n) : "memory")

#define LDSM4(r0, r1, r2, r3, addr) \
    asm volatile("ldmatrix.sync.aligned.m8n8.x4.shared.b16 {%0,%1,%2,%3}, [%4];" \
                 : "=r"(r0), "=r"(r1), "=r"(r2), "=r"(r3) : "r"(addr))

#define STG_CS_F2(ptr, v0, v1) \
    asm volatile("st.global.cs.v2.f32 [%0], {%1, %2};" \
                 :: "l"(ptr), "f"(v0), "f"(v1) : "memory")

__device__ __forceinline__ void mma16816(float* c, const uint32_t* a, const uint32_t* b) {
    asm volatile(
        "mma.sync.aligned.m16n8k16.row.col.f32.f16.f16.f32 "
        "{%0,%1,%2,%3}, {%4,%5,%6,%7}, {%8,%9}, {%0,%1,%2,%3};"
        : "+f"(c[0]), "+f"(c[1]), "+f"(c[2]), "+f"(c[3])
        : "r"(a[0]), "r"(a[1]), "r"(a[2]), "r"(a[3]), "r"(b[0]), "r"(b[1]));
}

// ---------------------------------------------------------------------------
// Fused converter: blocks [0, XB) convert X fp32->fp16 (8/thread),
// blocks [XB, XB+WB) dequant W via codebook (4/thread).
// ---------------------------------------------------------------------------
#define XBLOCKS 32768
#define WBLOCKS 16384

__device__ __forceinline__ uint32_t h2u(__half2 h) {
    return *reinterpret_cast<uint32_t*>(&h);
}

__global__ void __launch_bounds__(256) convert_kernel(const float* __restrict__ x,
                                                      const int* __restrict__ idx,
                                                      const float* __restrict__ scale,
                                                      const float* __restrict__ lut) {
    if (blockIdx.x < XBLOCKS) {
        size_t i = ((size_t)blockIdx.x * 256 + threadIdx.x) * 8;
        float4 a = *reinterpret_cast<const float4*>(x + i);
        float4 b = *reinterpret_cast<const float4*>(x + i + 4);
        uint4 o;
        o.x = h2u(__floats2half2_rn(a.x, a.y));
        o.y = h2u(__floats2half2_rn(a.z, a.w));
        o.z = h2u(__floats2half2_rn(b.x, b.y));
        o.w = h2u(__floats2half2_rn(b.z, b.w));
        *reinterpret_cast<uint4*>(g_X + i) = o;
    } else {
        __shared__ float slut[CODES];
        if (threadIdx.x < CODES) slut[threadIdx.x] = lut[threadIdx.x];
        __syncthreads();
        size_t i = ((size_t)(blockIdx.x - XBLOCKS) * 256 + threadIdx.x) * 4;
        int4 v = *reinterpret_cast<const int4*>(idx + i);
        float s = scale[i >> 12];   // K_TOTAL elements per output row
        uint2 o;
        o.x = h2u(__floats2half2_rn(slut[v.x] * s, slut[v.y] * s));
        o.y = h2u(__floats2half2_rn(slut[v.z] * s, slut[v.w] * s));
        *reinterpret_cast<uint2*>(g_W + i) = o;
    }
}

// ---------------------------------------------------------------------------
// Persistent GEMM: 148 CTAs; each walks tiles bid, bid+148, ...
// CTA tile = 128(M) x 256(N); BK=128, 2 smem stages; 8 warps (2M x 4N),
// warp tile 64x64; fragment double-buffer pipelined across kit AND tile
// boundaries (next tile's stage 0 loads overlap this tile's epilogue).
// ---------------------------------------------------------------------------
__global__ void __launch_bounds__(256, 1) gemm_kernel(const __half* __restrict__ X,
                                                      const __half* __restrict__ W,
                                                      float* __restrict__ out) {
    extern __shared__ __half sm[];
    const uint32_t smem_base = smem_u32(sm);
    const int tid  = threadIdx.x;
    const int lane = tid & 31;
    const int wid  = tid >> 5;
    const int warp_m = wid & 1;    // 64-row band
    const int warp_n = wid >> 1;   // 64-col band (0..3)

    // --- cp.async mapping: chunk q -> row = (tid>>4) + 16q, col = (tid&15)*8
    const int crow = tid >> 4, ccol = tid & 15;
    const size_t   offA  = (size_t)crow * K_TOTAL + ccol * 8;   // same for B
    const uint32_t dA    = (uint32_t)(crow * BKP + ccol * 8) * 2;
    const uint32_t dB    = (uint32_t)(A_STAGE_HALFS + crow * BKP + ccol * 8) * 2;
    const size_t   gstep = (size_t)16 * K_TOTAL;
    const uint32_t dstep = (uint32_t)(16 * BKP) * 2;

    // --- ldmatrix per-thread byte offsets within a stage ---
    const uint32_t a_off0 = (uint32_t)((warp_m * 64 + (lane & 15)) * BKP
                                       + (lane >> 4) * 8) * 2;
    const uint32_t b_off0 = (uint32_t)(A_STAGE_HALFS * 2)
        + (uint32_t)((warp_n * 64 + (lane & 7) + ((lane >> 4) & 1) * 8) * BKP
                     + ((lane >> 3) & 1) * 8) * 2;

    float acc[4][8][4];
    uint32_t a[2][4][4], b[2][8][2];

    #define LOAD_FRAGS(bf, sb, colk) do {                                      \
        const uint32_t _aB = (sb) + a_off0 + (uint32_t)((colk) * 16 * 2);      \
        const uint32_t _bB = (sb) + b_off0 + (uint32_t)((colk) * 16 * 2);      \
        _Pragma("unroll")                                                      \
        for (int _t = 0; _t < 4; _t++)                                         \
            LDSM4(a[bf][_t][0], a[bf][_t][1], a[bf][_t][2], a[bf][_t][3],      \
                  _aB + (uint32_t)(_t * 16 * BKP) * 2);                        \
        _Pragma("unroll")                                                      \
        for (int _jj = 0; _jj < 4; _jj++)                                      \
            LDSM4(b[bf][_jj * 2][0], b[bf][_jj * 2][1],                        \
                  b[bf][_jj * 2 + 1][0], b[bf][_jj * 2 + 1][1],                \
                  _bB + (uint32_t)(_jj * 16 * BKP) * 2);                       \
    } while (0)

    int tile = blockIdx.x;

    // --- prologue: fill stage 0 of the first tile ---
    {
        const int m_base = (tile >> 4) * BM;   // NTX = 16
        const int n_base = (tile & 15) * BN;
        const __half* pA = X + (size_t)m_base * K_TOTAL + offA;
        const __half* pB = W + (size_t)n_base * K_TOTAL + offA;
        #pragma unroll
        for (int q = 0; q < 8; q++)  CP_ASYNC16(smem_base + dA + q * dstep, pA + q * gstep);
        #pragma unroll
        for (int q = 0; q < 16; q++) CP_ASYNC16(smem_base + dB + q * dstep, pB + q * gstep);
        CP_COMMIT();
    }
    CP_WAIT(0);
    __syncthreads();
    LOAD_FRAGS(0, smem_base, 0);

    // --- persistent tile loop ---
    while (true) {
        const int m_base = (tile >> 4) * BM;
        const int n_base = (tile & 15) * BN;
        const __half* gA = X + (size_t)m_base * K_TOTAL + offA;
        const __half* gB = W + (size_t)n_base * K_TOTAL + offA;

        const int  next_tile = tile + GRID;
        const bool has_next_tile = next_tile < NTILES;
        const __half* nA = has_next_tile
            ? X + (size_t)((next_tile >> 4) * BM) * K_TOTAL + offA : gA;
        const __half* nB = has_next_tile
            ? W + (size_t)((next_tile & 15) * BN) * K_TOTAL + offA : gB;

        #pragma unroll
        for (int t = 0; t < 4; t++)
            #pragma unroll
            for (int j = 0; j < 8; j++)
                #pragma unroll
                for (int e = 0; e < 4; e++) acc[t][j][e] = 0.f;

        for (int kit = 0; kit < NITER; kit++) {
            const uint32_t sb  = smem_base + (uint32_t)((kit & 1) * STAGE_HALFS) * 2;
            const uint32_t sb2 = smem_base + (uint32_t)(((kit + 1) & 1) * STAGE_HALFS) * 2;
            const bool last_kit = (kit == NITER - 1);
            // prefetch source: next kit of this tile, or kit0 of next tile
            const __half* pA = last_kit ? nA : gA + (size_t)(kit + 1) * BK;
            const __half* pB = last_kit ? nB : gB + (size_t)(kit + 1) * BK;
            const bool do_pref = !last_kit || has_next_tile;

            #pragma unroll
            for (int ks = 0; ks < KS_PER_KIT; ks++) {
                const int cur = ks & 1, nxt = cur ^ 1;

                if (ks < 4 && do_pref) {   // 6 cp.async issues per step
                    #pragma unroll
                    for (int u = 0; u < 2; u++) {
                        int q = 2 * ks + u;
                        CP_ASYNC16(sb2 + dA + q * dstep, pA + q * gstep);
                    }
                    #pragma unroll
                    for (int u = 0; u < 4; u++) {
                        int q = 4 * ks + u;
                        CP_ASYNC16(sb2 + dB + q * dstep, pB + q * gstep);
                    }
                    if (ks == 3) CP_COMMIT();
                }

                if (ks < KS_PER_KIT - 1) {
                    LOAD_FRAGS(nxt, sb, ks + 1);
                } else if (do_pref) {
                    CP_WAIT(0);
                    __syncthreads();
                    LOAD_FRAGS(nxt, sb2, 0);
                }

                #pragma unroll
                for (int t = 0; t < 4; t++)
                    #pragma unroll
                    for (int j = 0; j < 8; j++)
                        mma16816(acc[t][j], a[cur][t], b[cur][j]);
            }
        }

        // --- epilogue (overlaps next tile's in-flight stage-0 copies) ---
        #pragma unroll
        for (int t = 0; t < 4; t++) {
            int row = m_base + warp_m * 64 + t * 16 + (lane >> 2);
            #pragma unroll
            for (int j = 0; j < 8; j++) {
                int col = n_base + warp_n * 64 + j * 8 + (lane & 3) * 2;
                float* p0 = out + (size_t)row * N_TOTAL + col;
                float* p1 = out + (size_t)(row + 8) * N_TOTAL + col;
                STG_CS_F2(p0, acc[t][j][0], acc[t][j][1]);
                STG_CS_F2(p1, acc[t][j][2], acc[t][j][3]);
            }
        }

        if (!has_next_tile) break;
        tile = next_tile;
    }
    #undef LOAD_FRAGS
}

// ---------------------------------------------------------------------------
// Host launcher
// ---------------------------------------------------------------------------
extern "C" void kernel_launch(void* const* d_in, const int* in_sizes, int n_in,
                              void* d_out, int out_size) {
    (void)in_sizes; (void)n_in; (void)out_size;
    const float* x     = (const float*)d_in[0];
    const float* scale = (const float*)d_in[1];
    const float* lut   = (const float*)d_in[2];
    const int*   idx   = (const int*)d_in[3];
    float* out = (float*)d_out;

    void *pX = nullptr, *pW = nullptr;
    cudaGetSymbolAddress(&pX, g_X);
    cudaGetSymbolAddress(&pW, g_W);

    cudaFuncSetAttribute(gemm_kernel, cudaFuncAttributeMaxDynamicSharedMemorySize,
                         SMEM_BYTES);

    convert_kernel<<<XBLOCKS + WBLOCKS, 256>>>(x, idx, scale, lut);

    gemm_kernel<<<GRID, 256, SMEM_BYTES>>>((const __half*)pX, (const __half*)pW, out);
}